// round 2
// baseline (speedup 1.0000x reference)
#include <cuda_runtime.h>
#include <cstdint>

#define NN   100000
#define EE   1600000
#define BBG  64
#define DINV 9
#define HH   128
#define EPSV 1e-5f

#define SCAN_BS 512
#define SCAN_NB ((NN + SCAN_BS - 1) / SCAN_BS)   // 196

// ---------------- scratch (device globals; no allocation) ----------------
__device__ float    g_h0[NN * HH];
__device__ float    g_h1[NN * HH];
__device__ float    g_agg[NN * HH];
__device__ int      g_rowptr[NN + 1];
__device__ int      g_cursor[NN];
__device__ int      g_cnt[NN];
__device__ int      g_col[EE];
__device__ int      g_bsum[256];
__device__ float    g_gsum[BBG * HH];
__device__ unsigned g_gmax[BBG * HH];
__device__ int      g_gcnt[BBG];

// ---------------- epilogue: LayerNorm + ReLU + store ----------------
// One warp holds all 128 features of a node: lane l owns features 4l..4l+3.
__device__ __forceinline__ void ln_relu_store(float4 acc, int node, int lane,
                                              float4 gv, float4 bev,
                                              float* __restrict__ out, int nNodes)
{
    float s = acc.x + acc.y + acc.z + acc.w;
    float q = acc.x * acc.x + acc.y * acc.y + acc.z * acc.z + acc.w * acc.w;
#pragma unroll
    for (int off = 16; off; off >>= 1) {
        s += __shfl_xor_sync(0xffffffffu, s, off);
        q += __shfl_xor_sync(0xffffffffu, q, off);
    }
    float m  = s * (1.0f / HH);
    float v  = q * (1.0f / HH) - m * m;
    float rs = rsqrtf(v + EPSV);
    float4 y;
    y.x = fmaxf((acc.x - m) * rs * gv.x + bev.x, 0.0f);
    y.y = fmaxf((acc.y - m) * rs * gv.y + bev.y, 0.0f);
    y.z = fmaxf((acc.z - m) * rs * gv.z + bev.z, 0.0f);
    y.w = fmaxf((acc.w - m) * rs * gv.w + bev.w, 0.0f);
    if (node < nNodes)
        *(float4*)(out + (size_t)node * HH + lane * 4) = y;
}

// ---------------- node embedder: relu(LN(x @ W0^T + b0)) ----------------
// 64 nodes per block, 256 threads. warp w -> nodes 8w..8w+7; lane l -> feat 4l..4l+3.
__global__ void k_embed(const float* __restrict__ x, const float* __restrict__ W0,
                        const float* __restrict__ b0, const float* __restrict__ g0,
                        const float* __restrict__ be0, float* __restrict__ out, int nNodes)
{
    __shared__ float w0S[DINV * 132];   // [k][o] transposed, padded
    __shared__ float xS[64 * DINV];

    int tid  = threadIdx.x;
    int lane = tid & 31, warp = tid >> 5;
    int node0 = blockIdx.x * 64;

    for (int i = tid; i < DINV * HH; i += blockDim.x) {
        int k = i / HH, o = i % HH;
        w0S[k * 132 + o] = W0[o * DINV + k];
    }
    for (int i = tid; i < 64 * DINV; i += blockDim.x) {
        int gidx = node0 * DINV + i;
        xS[i] = (gidx < nNodes * DINV) ? x[gidx] : 0.0f;
    }
    __syncthreads();

    float4 acc[8];
#pragma unroll
    for (int n = 0; n < 8; n++) acc[n] = make_float4(0.f, 0.f, 0.f, 0.f);

    int nb = warp * 8;
#pragma unroll
    for (int k = 0; k < DINV; k++) {
        float4 wv = *(const float4*)(w0S + k * 132 + lane * 4);
#pragma unroll
        for (int n = 0; n < 8; n++) {
            float a = xS[(nb + n) * DINV + k];
            acc[n].x += a * wv.x; acc[n].y += a * wv.y;
            acc[n].z += a * wv.z; acc[n].w += a * wv.w;
        }
    }

    float4 bv  = *(const float4*)(b0 + lane * 4);
    float4 gv  = *(const float4*)(g0 + lane * 4);
    float4 bev = *(const float4*)(be0 + lane * 4);
#pragma unroll
    for (int n = 0; n < 8; n++) {
        acc[n].x += bv.x; acc[n].y += bv.y; acc[n].z += bv.z; acc[n].w += bv.w;
        ln_relu_store(acc[n], node0 + nb + n, lane, gv, bev, out, nNodes);
    }
}

// ---------------- CSR build ----------------
__global__ void k_zero_cnt() {
    for (int i = blockIdx.x * blockDim.x + threadIdx.x; i < NN; i += gridDim.x * blockDim.x)
        g_cnt[i] = 0;
}

__global__ void k_count(const int* __restrict__ dst) {
    int e = blockIdx.x * blockDim.x + threadIdx.x;
    if (e < EE) atomicAdd(&g_cnt[dst[e]], 1);
}

__global__ void k_scan1() {
    __shared__ int s[SCAN_BS];
    int t = threadIdx.x;
    int i = blockIdx.x * SCAN_BS + t;
    int val = (i < NN) ? g_cnt[i] : 0;
    s[t] = val;
    __syncthreads();
#pragma unroll
    for (int off = 1; off < SCAN_BS; off <<= 1) {
        int xx = (t >= off) ? s[t - off] : 0;
        __syncthreads();
        s[t] += xx;
        __syncthreads();
    }
    if (i < NN) g_rowptr[i + 1] = s[t];          // raw inclusive (no block offset yet)
    if (t == SCAN_BS - 1) g_bsum[blockIdx.x] = s[t];
}

__global__ void k_scan2() {
    int run = 0;
    for (int b = 0; b < SCAN_NB; b++) {
        int t = g_bsum[b];
        g_bsum[b] = run;
        run += t;
    }
    g_rowptr[0] = 0;
}

__global__ void k_scan3() {
    for (int i = blockIdx.x * blockDim.x + threadIdx.x; i < NN; i += gridDim.x * blockDim.x)
        g_rowptr[i + 1] += g_bsum[i / SCAN_BS];
}

__global__ void k_cursor() {
    for (int i = blockIdx.x * blockDim.x + threadIdx.x; i < NN; i += gridDim.x * blockDim.x)
        g_cursor[i] = g_rowptr[i];
}

__global__ void k_fill(const int* __restrict__ src, const int* __restrict__ dst) {
    int e = blockIdx.x * blockDim.x + threadIdx.x;
    if (e < EE) {
        int d = dst[e];
        int p = atomicAdd(&g_cursor[d], 1);
        g_col[p] = src[e];
    }
}

// ---------------- pull-based mean aggregation ----------------
// 2 nodes per block of 256: thread = (node_sub, feature). Coalesced 512B per edge.
__global__ void k_agg(const float* __restrict__ hin, float* __restrict__ agg) {
    int node = blockIdx.x * 2 + (threadIdx.x >> 7);
    int f    = threadIdx.x & 127;
    int beg = g_rowptr[node], end = g_rowptr[node + 1];
    float s = 0.0f;
    int j = beg;
    for (; j + 4 <= end; j += 4) {
        int c0 = g_col[j], c1 = g_col[j + 1], c2 = g_col[j + 2], c3 = g_col[j + 3];
        s += hin[(size_t)c0 * HH + f];
        s += hin[(size_t)c1 * HH + f];
        s += hin[(size_t)c2 * HH + f];
        s += hin[(size_t)c3 * HH + f];
    }
    for (; j < end; j++) s += hin[(size_t)g_col[j] * HH + f];
    float d = (float)(end - beg);
    agg[(size_t)node * HH + f] = s / fmaxf(d, 1.0f);
}

// ---------------- fused dual-GEMM + LN + ReLU ----------------
// out = relu(LN(agg@Wl^T + bl + h@Wr^T)); tile 64 nodes x 128 feats, 256 threads.
__global__ void __launch_bounds__(256)
k_gemm_ln(const float* __restrict__ A, const float* __restrict__ Hin,
          const float* __restrict__ Wl, const float* __restrict__ bl,
          const float* __restrict__ Wr,
          const float* __restrict__ gam, const float* __restrict__ bet,
          float* __restrict__ out, int nNodes)
{
    __shared__ float inS[64 * 32];
    __shared__ float wS[32 * 132];

    int tid  = threadIdx.x;
    int lane = tid & 31, warp = tid >> 5;
    int node0 = blockIdx.x * 64;

    float4 acc[8];
#pragma unroll
    for (int n = 0; n < 8; n++) acc[n] = make_float4(0.f, 0.f, 0.f, 0.f);

#pragma unroll 1
    for (int c = 0; c < 8; c++) {
        const float* src = (c < 4) ? A : Hin;
        const float* W   = (c < 4) ? Wl : Wr;
        int k0 = (c & 3) * 32;

        // stage input tile [64][32]
        {
            int r  = tid >> 3;
            int c4 = (tid & 7) * 4;
#pragma unroll
            for (int it = 0; it < 2; it++) {
                int row  = r + it * 32;
                int node = node0 + row;
                if (node >= nNodes) node = nNodes - 1;
                float4 v = *(const float4*)(src + (size_t)node * HH + k0 + c4);
                *(float4*)(inS + row * 32 + c4) = v;
            }
        }
        // stage transposed weight tile wS[kk][o] = W[o][k0+kk]
        {
            int kk4 = (tid & 7) * 4;
            int o0  = tid >> 3;
#pragma unroll
            for (int it = 0; it < 4; it++) {
                int o = o0 + it * 32;
                float4 v = *(const float4*)(W + o * HH + k0 + kk4);
                wS[(kk4 + 0) * 132 + o] = v.x;
                wS[(kk4 + 1) * 132 + o] = v.y;
                wS[(kk4 + 2) * 132 + o] = v.z;
                wS[(kk4 + 3) * 132 + o] = v.w;
            }
        }
        __syncthreads();

        int nb = warp * 8;
#pragma unroll
        for (int kk = 0; kk < 32; kk += 4) {
            float4 iv[8];
#pragma unroll
            for (int n = 0; n < 8; n++)
                iv[n] = *(const float4*)(inS + (nb + n) * 32 + kk);
#pragma unroll
            for (int dk = 0; dk < 4; dk++) {
                float4 wv = *(const float4*)(wS + (kk + dk) * 132 + lane * 4);
#pragma unroll
                for (int n = 0; n < 8; n++) {
                    float a = (dk == 0) ? iv[n].x : (dk == 1) ? iv[n].y
                            : (dk == 2) ? iv[n].z : iv[n].w;
                    acc[n].x += a * wv.x; acc[n].y += a * wv.y;
                    acc[n].z += a * wv.z; acc[n].w += a * wv.w;
                }
            }
        }
        __syncthreads();
    }

    float4 bv  = *(const float4*)(bl + lane * 4);
    float4 gv  = *(const float4*)(gam + lane * 4);
    float4 bev = *(const float4*)(bet + lane * 4);
    int nb = warp * 8;
#pragma unroll
    for (int n = 0; n < 8; n++) {
        acc[n].x += bv.x; acc[n].y += bv.y; acc[n].z += bv.z; acc[n].w += bv.w;
        ln_relu_store(acc[n], node0 + nb + n, lane, gv, bev, out, nNodes);
    }
}

// ---------------- pooling ----------------
__global__ void k_zero_pool() {
    int i = blockIdx.x * blockDim.x + threadIdx.x;
    if (i < BBG * HH) { g_gsum[i] = 0.0f; g_gmax[i] = 0u; }
    if (i < BBG) g_gcnt[i] = 0;
}

__global__ void k_pool(const float* __restrict__ ne, const int* __restrict__ batch) {
    int node = blockIdx.x * 2 + (threadIdx.x >> 7);
    int f    = threadIdx.x & 127;
    int b = batch[node];
    float v = ne[(size_t)node * HH + f];
    atomicAdd(&g_gsum[b * HH + f], v);
    atomicMax(&g_gmax[b * HH + f], __float_as_uint(v));   // v >= 0 post-ReLU
    if (f == 0) atomicAdd(&g_gcnt[b], 1);
}

__global__ void k_pool_final(float* __restrict__ out) {
    int b = blockIdx.x, f = threadIdx.x;
    float cnt = fmaxf((float)g_gcnt[b], 1.0f);
    out[(size_t)NN * HH + b * 2 * HH + f]      = g_gsum[b * HH + f] / cnt;
    out[(size_t)NN * HH + b * 2 * HH + HH + f] = __uint_as_float(g_gmax[b * HH + f]);
}

// ---------------- launch ----------------
extern "C" void kernel_launch(void* const* d_in, const int* in_sizes, int n_in,
                              void* d_out, int out_size)
{
    const float* x    = (const float*)d_in[0];
    const int*   ei   = (const int*)d_in[1];
    const int*   bat  = (const int*)d_in[2];
    const float* W0   = (const float*)d_in[3];
    const float* b0   = (const float*)d_in[4];
    const float* g0   = (const float*)d_in[5];
    const float* be0  = (const float*)d_in[6];
    const float* Wl1  = (const float*)d_in[7];
    const float* bl1  = (const float*)d_in[8];
    const float* Wr1  = (const float*)d_in[9];
    const float* g1   = (const float*)d_in[10];
    const float* be1  = (const float*)d_in[11];
    const float* Wl2  = (const float*)d_in[12];
    const float* bl2  = (const float*)d_in[13];
    const float* Wr2  = (const float*)d_in[14];
    const float* g2   = (const float*)d_in[15];
    const float* be2  = (const float*)d_in[16];
    const float* Wl3  = (const float*)d_in[17];
    const float* bl3  = (const float*)d_in[18];
    const float* Wr3  = (const float*)d_in[19];
    const float* g3   = (const float*)d_in[20];
    const float* be3  = (const float*)d_in[21];
    float* out = (float*)d_out;

    const int* src = ei;        // edge_index[0]
    const int* dst = ei + EE;   // edge_index[1]

    float* h0;  cudaGetSymbolAddress((void**)&h0,  g_h0);
    float* h1;  cudaGetSymbolAddress((void**)&h1,  g_h1);
    float* agg; cudaGetSymbolAddress((void**)&agg, g_agg);

    int nodeBlocks = (NN + 63) / 64;          // 1563
    int edgeBlocks = (EE + 255) / 256;        // 6250

    // node embedder -> h0
    k_embed<<<nodeBlocks, 256>>>(x, W0, b0, g0, be0, h0, NN);

    // CSR build (dst-indexed)
    k_zero_cnt<<<256, 256>>>();
    k_count<<<edgeBlocks, 256>>>(dst);
    k_scan1<<<SCAN_NB, SCAN_BS>>>();
    k_scan2<<<1, 1>>>();
    k_scan3<<<256, 256>>>();
    k_cursor<<<256, 256>>>();
    k_fill<<<edgeBlocks, 256>>>(src, dst);

    // layer 1: h0 -> h1
    k_agg<<<NN / 2, 256>>>(h0, agg);
    k_gemm_ln<<<nodeBlocks, 256>>>(agg, h0, Wl1, bl1, Wr1, g1, be1, h1, NN);
    // layer 2: h1 -> h0
    k_agg<<<NN / 2, 256>>>(h1, agg);
    k_gemm_ln<<<nodeBlocks, 256>>>(agg, h1, Wl2, bl2, Wr2, g2, be2, h0, NN);
    // layer 3: h0 -> node_embed (d_out)
    k_agg<<<NN / 2, 256>>>(h0, agg);
    k_gemm_ln<<<nodeBlocks, 256>>>(agg, h0, Wl3, bl3, Wr3, g3, be3, out, NN);

    // pooling
    k_zero_pool<<<(BBG * HH + 255) / 256, 256>>>();
    k_pool<<<NN / 2, 256>>>(out, bat);
    k_pool_final<<<BBG, HH>>>(out);
}